// round 13
// baseline (speedup 1.0000x reference)
#include <cuda_runtime.h>
#include <cuda_bf16.h>

// 3x3 stride-2 VALID average pooling, fp32.
// x: (8, 64, 512, 512) -> out: (8, 64, 255, 255)

#define IN_H 512
#define IN_W 512
#define OUT_H 255
#define OUT_W 255
#define ROWS_PER_BLOCK 8                    // output rows per CTA
#define IN_ROWS (2 * ROWS_PER_BLOCK + 1)    // 17 input rows staged
#define NTHREADS 256
#define STAGE_ELEMS (IN_ROWS * (IN_W / 4))  // 17 * 128 = 2176 float4 elements

__global__ __launch_bounds__(NTHREADS)
void KeyedAvgpool2d_2413771620972_kernel(const float* __restrict__ x,
                                         float* __restrict__ out)
{
    __shared__ float s[IN_ROWS][IN_W];

    const int rb  = blockIdx.x;   // row-block within plane (fast axis -> L2 reuse of boundary row)
    const int nc  = blockIdx.y;   // plane index (N*C)
    const int tid = threadIdx.x;

    const int ih0 = rb * (2 * ROWS_PER_BLOCK);   // first input row this CTA needs

    // ---- Stage IN_ROWS x IN_W floats into smem with float4 loads ----
    // 2176 float4 / 256 threads = 8.5 iterations; explicit unroll so ptxas
    // front-batches the LDG.128s (high MLP before the smem stores).
    const float4* __restrict__ x4 =
        reinterpret_cast<const float4*>(x + (size_t)nc * IN_H * IN_W);

    #pragma unroll
    for (int it = 0; it < 9; it++) {
        const int i = tid + it * NTHREADS;
        if (i < STAGE_ELEMS) {
            const int r  = i >> 7;        // i / 128
            const int c4 = i & 127;       // i % 128
            const int ih = ih0 + r;
            if (ih < IN_H) {
                float4 v = x4[(size_t)ih * (IN_W / 4) + c4];
                *reinterpret_cast<float4*>(&s[r][c4 * 4]) = v;
            }
        }
    }
    __syncthreads();

    // ---- Compute: each thread owns one output column ----
    if (tid < OUT_W) {
        const int iw = 2 * tid;
        const float inv9 = 1.0f / 9.0f;
        float* __restrict__ op =
            out + (size_t)nc * OUT_H * OUT_W + (size_t)(rb * ROWS_PER_BLOCK) * OUT_W + tid;

        // Horizontal triple-sums per staged row; each even row's sum is
        // reused by the two vertically-adjacent output rows.
        float hs[IN_ROWS];
        #pragma unroll
        for (int r = 0; r < IN_ROWS; r++) {
            hs[r] = s[r][iw] + s[r][iw + 1] + s[r][iw + 2];
        }

        #pragma unroll
        for (int r = 0; r < ROWS_PER_BLOCK; r++) {
            const int oh = rb * ROWS_PER_BLOCK + r;
            if (oh < OUT_H) {
                float sum = hs[2 * r] + hs[2 * r + 1] + hs[2 * r + 2];
                op[(size_t)r * OUT_W] = sum * inv9;
            }
        }
    }
}

extern "C" void kernel_launch(void* const* d_in, const int* in_sizes, int n_in,
                              void* d_out, int out_size)
{
    const float* x = (const float*)d_in[0];
    float* out = (float*)d_out;

    dim3 grid((OUT_H + ROWS_PER_BLOCK - 1) / ROWS_PER_BLOCK,
              in_sizes[0] / (IN_H * IN_W));   // 32 x 512
    KeyedAvgpool2d_2413771620972_kernel<<<grid, NTHREADS>>>(x, out);
}

// round 14
// speedup vs baseline: 1.2612x; 1.2612x over previous
#include <cuda_runtime.h>
#include <cuda_bf16.h>

// 3x3 stride-2 VALID average pooling, fp32.
// x: (8, 64, 512, 512) -> out: (8, 64, 255, 255)
//
// Barrier-free register-rolling design: no smem, no __syncthreads.
// Thread t owns output cols (2t, 2t+1) <- input cols 4t..4t+4:
//   one float4 load (row coverage exact, coalesced) + one scalar load of
//   element 4t+4 (L1-hot: adjacent warp's line, fetched same instruction).
// Vertical 3-row overlap handled by carrying the shared row's horizontal
// pair-sums in registers -> each input row read exactly once per strip.

#define IN_H 512
#define IN_W 512
#define OUT_H 255
#define OUT_W 255
#define RPB 15          // output rows per CTA (255 = 15 * 17, exact)
#define STRIPS 17
#define NT 128          // 128 threads x 2 cols = 256 >= 255 cols

__global__ __launch_bounds__(NT)
void KeyedAvgpool2d_2413771620972_kernel(const float* __restrict__ x,
                                         float* __restrict__ out)
{
    const int rb = blockIdx.x;    // strip within plane (fast axis: boundary-row L2 reuse)
    const int nc = blockIdx.y;    // plane (N*C)
    const int t  = threadIdx.x;

    const float*  __restrict__ plane = x + (size_t)nc * IN_H * IN_W;
    const float4* __restrict__ p4    = reinterpret_cast<const float4*>(plane);

    const bool full = (t < NT - 1);   // t==127: ow1=255 invalid, elem 4t+4=512 OOB
    const int  oh0  = rb * RPB;
    const float inv9 = 1.0f / 9.0f;

    // Carried horizontal pair-sums of input row 2*oh0 (shared top row).
    float a_c, b_c;
    {
        const int ih = 2 * oh0;
        float4 v = p4[(size_t)ih * (IN_W / 4) + t];
        float  e = full ? plane[(size_t)ih * IN_W + 4 * t + 4] : 0.0f;
        a_c = v.x + v.y + v.z;        // cols 4t..4t+2  -> output 2t
        b_c = v.z + v.w + e;          // cols 4t+2..4t+4 -> output 2t+1
    }

    float* __restrict__ op =
        out + (size_t)nc * OUT_H * OUT_W + (size_t)oh0 * OUT_W + 2 * t;

    #pragma unroll
    for (int r = 0; r < RPB; r++) {
        const int ih1 = 2 * (oh0 + r) + 1;

        // Two fresh input rows per output row (read-once property).
        float4 v1 = p4[(size_t)ih1 * (IN_W / 4) + t];
        float4 v2 = p4[(size_t)(ih1 + 1) * (IN_W / 4) + t];
        float  e1 = full ? plane[(size_t)ih1 * IN_W + 4 * t + 4] : 0.0f;
        float  e2 = full ? plane[(size_t)(ih1 + 1) * IN_W + 4 * t + 4] : 0.0f;

        const float a1 = v1.x + v1.y + v1.z, b1 = v1.z + v1.w + e1;
        const float a2 = v2.x + v2.y + v2.z, b2 = v2.z + v2.w + e2;

        op[0] = (a_c + a1 + a2) * inv9;
        if (full) op[1] = (b_c + b1 + b2) * inv9;

        a_c = a2;                     // bottom row becomes next top row
        b_c = b2;
        op += OUT_W;
    }
}

extern "C" void kernel_launch(void* const* d_in, const int* in_sizes, int n_in,
                              void* d_out, int out_size)
{
    const float* x = (const float*)d_in[0];
    float* out = (float*)d_out;

    dim3 grid(STRIPS, in_sizes[0] / (IN_H * IN_W));   // 17 x 512
    KeyedAvgpool2d_2413771620972_kernel<<<grid, NT>>>(x, out);
}